// round 1
// baseline (speedup 1.0000x reference)
#include <cuda_runtime.h>
#include <math.h>

#define Bsz   4
#define Nseq  2048
#define Emb   512
#define Hn    8
#define HDm   64
#define HID   1536
#define ROWS  (Bsz * Nseq)   // 8192

// ---------------- scratch (device globals; no allocation allowed) ----------
__device__ float g_xn [ROWS * Emb];       // 16 MB : LN1 out, then reused as attn out
__device__ float g_qkv[ROWS * 3 * Emb];   // 48 MB
__device__ float g_x1 [ROWS * Emb];       // 16 MB : residual after attention
__device__ float g_xn2[ROWS * Emb];       // 16 MB : LN2 out
__device__ float g_hid[ROWS * HID];       // 48 MB : FFN hidden

// ---------------- LayerNorm (optionally fused residual add) ----------------
// one block per row, 256 threads, 2 floats/thread (E = 512)
__global__ void __launch_bounds__(256) ln_kernel(
    const float* __restrict__ x, const float* __restrict__ resid,
    const float* __restrict__ g, const float* __restrict__ bb,
    float* __restrict__ out, float* __restrict__ xsum)
{
    int row = blockIdx.x;
    int tid = threadIdx.x;
    const float2* xr = (const float2*)(x + (size_t)row * Emb);
    float2 v = xr[tid];
    if (resid) {
        const float2* rr = (const float2*)(resid + (size_t)row * Emb);
        float2 r = rr[tid];
        v.x += r.x; v.y += r.y;
        ((float2*)(xsum + (size_t)row * Emb))[tid] = v;
    }
    float s  = v.x + v.y;
    float sq = v.x * v.x + v.y * v.y;
    #pragma unroll
    for (int o = 16; o > 0; o >>= 1) {
        s  += __shfl_xor_sync(0xffffffffu, s,  o);
        sq += __shfl_xor_sync(0xffffffffu, sq, o);
    }
    __shared__ float ss[8], sqs[8];
    int w = tid >> 5, lane = tid & 31;
    if (lane == 0) { ss[w] = s; sqs[w] = sq; }
    __syncthreads();
    float st = 0.f, sqt = 0.f;
    #pragma unroll
    for (int i = 0; i < 8; i++) { st += ss[i]; sqt += sqs[i]; }
    float mu   = st * (1.0f / Emb);
    float var  = sqt * (1.0f / Emb) - mu * mu;
    float rstd = rsqrtf(var + 1e-5f);
    float2 gg  = ((const float2*)g)[tid];
    float2 bv  = ((const float2*)bb)[tid];
    float2 o;
    o.x = (v.x - mu) * rstd * gg.x + bv.x;
    o.y = (v.y - mu) * rstd * gg.y + bv.y;
    ((float2*)(out + (size_t)row * Emb))[tid] = o;
}

// ---------------- GELU (exact, erf) ----------------------------------------
__device__ __forceinline__ float gelu_exact(float x) {
    return 0.5f * x * (1.0f + erff(x * 0.70710678118654752f));
}

// ---------------- tiled SGEMM: C = A[M,K] @ W[K,N] + bias (+gelu)(+resid) --
// BM=BN=128, BK=16, 256 threads, 8x8 per thread
template<int ACT, bool RES>
__global__ void __launch_bounds__(256) gemm_kernel(
    const float* __restrict__ A, const float* __restrict__ W,
    const float* __restrict__ bias, const float* __restrict__ R,
    float* __restrict__ C, int M, int K, int N)
{
    __shared__ float As[16][129];
    __shared__ float Bs[16][128];
    int tid = threadIdx.x;
    int bm = blockIdx.y, bn = blockIdx.x;
    int ty = tid >> 4, tx = tid & 15;
    float acc[8][8] = {};
    int ar = tid >> 2;            // 0..63
    int ac = (tid & 3) * 4;       // 0,4,8,12
    int br = tid >> 5;            // 0..7
    int bc = (tid & 31) * 4;      // 0..124
    const float* Ap = A + ((size_t)bm * 128 + ar) * K + ac;
    const float* Wp = W + (size_t)br * N + (size_t)bn * 128 + bc;

    for (int k0 = 0; k0 < K; k0 += 16) {
        float4 a0 = *(const float4*)(Ap + k0);
        float4 a1 = *(const float4*)(Ap + (size_t)64 * K + k0);
        float4 b0 = *(const float4*)(Wp + (size_t)k0 * N);
        float4 b1 = *(const float4*)(Wp + (size_t)(k0 + 8) * N);
        As[ac + 0][ar] = a0.x; As[ac + 1][ar] = a0.y;
        As[ac + 2][ar] = a0.z; As[ac + 3][ar] = a0.w;
        As[ac + 0][ar + 64] = a1.x; As[ac + 1][ar + 64] = a1.y;
        As[ac + 2][ar + 64] = a1.z; As[ac + 3][ar + 64] = a1.w;
        *(float4*)&Bs[br][bc]     = b0;
        *(float4*)&Bs[br + 8][bc] = b1;
        __syncthreads();
        #pragma unroll
        for (int k = 0; k < 16; k++) {
            float am[8], bnv[8];
            #pragma unroll
            for (int i = 0; i < 8; i++) am[i]  = As[k][ty * 8 + i];
            #pragma unroll
            for (int j = 0; j < 8; j++) bnv[j] = Bs[k][tx * 8 + j];
            #pragma unroll
            for (int i = 0; i < 8; i++)
                #pragma unroll
                for (int j = 0; j < 8; j++)
                    acc[i][j] = fmaf(am[i], bnv[j], acc[i][j]);
        }
        __syncthreads();
    }

    #pragma unroll
    for (int i = 0; i < 8; i++) {
        int row = bm * 128 + ty * 8 + i;
        #pragma unroll
        for (int j = 0; j < 8; j += 4) {
            int col = bn * 128 + tx * 8 + j;
            float4 r;
            r.x = acc[i][j]     + bias[col];
            r.y = acc[i][j + 1] + bias[col + 1];
            r.z = acc[i][j + 2] + bias[col + 2];
            r.w = acc[i][j + 3] + bias[col + 3];
            if (ACT == 1) {
                r.x = gelu_exact(r.x); r.y = gelu_exact(r.y);
                r.z = gelu_exact(r.z); r.w = gelu_exact(r.w);
            }
            if (RES) {
                float4 rv = *(const float4*)&R[(size_t)row * N + col];
                r.x += rv.x; r.y += rv.y; r.z += rv.z; r.w += rv.w;
            }
            *(float4*)&C[(size_t)row * N + col] = r;
        }
    }
}

// ---------------- flash attention, fp32 ------------------------------------
// grid = (N/64, B*H), block = 256.  Q tile 64x64 resident; stream K/V in
// 64-row blocks with online softmax.  Thread owns 4 rows x 4 cols:
//   S/P cols strided  (tx + 16j)  -> conflict-free Ks float4 reads along d
//   O   cols contiguous (tx*4+j)  -> conflict-free Vs float4 reads
#define AS 68   // smem row stride (floats), padded

__global__ void __launch_bounds__(256) attn_kernel(
    const float* __restrict__ qkv, float* __restrict__ out)
{
    extern __shared__ float sm[];
    float* Qs = sm;
    float* Ks = Qs + 64 * AS;
    float* Vs = Ks + 64 * AS;
    float* Ps = Vs + 64 * AS;

    int tid = threadIdx.x;
    int bh = blockIdx.y;
    int b = bh >> 3, h = bh & 7;
    int q0 = blockIdx.x * 64;
    const float* base = qkv + (size_t)b * Nseq * (3 * Emb) + h * (3 * HDm);

    // load Q tile (coalesced float2)
    #pragma unroll
    for (int r = 0; r < 8; r++) {
        int fi  = tid + r * 256;
        int row = fi >> 5;
        int c2  = (fi & 31) * 2;
        float2 v = *(const float2*)(base + (size_t)(q0 + row) * (3 * Emb) + c2);
        *(float2*)&Qs[row * AS + c2] = v;
    }

    int ty = tid >> 4;   // row group: rows ty*4 .. ty*4+3
    int tx = tid & 15;
    float O[4][4] = {};
    float m[4], l[4];
    #pragma unroll
    for (int i = 0; i < 4; i++) { m[i] = -1e30f; l[i] = 0.f; }

    for (int kb = 0; kb < Nseq / 64; kb++) {
        __syncthreads();   // protect Ks/Vs still being read by previous iter
        #pragma unroll
        for (int r = 0; r < 8; r++) {
            int fi  = tid + r * 256;
            int row = fi >> 5;
            int c2  = (fi & 31) * 2;
            const float* gp = base + (size_t)(kb * 64 + row) * (3 * Emb);
            *(float2*)&Ks[row * AS + c2] = *(const float2*)(gp + HDm + c2);
            *(float2*)&Vs[row * AS + c2] = *(const float2*)(gp + 2 * HDm + c2);
        }
        __syncthreads();

        // ---- S = Q K^T (cols c_j = tx + 16j) ----
        float s[4][4] = {};
        #pragma unroll
        for (int d0 = 0; d0 < 64; d0 += 4) {
            float4 q[4], k[4];
            #pragma unroll
            for (int i = 0; i < 4; i++) q[i] = *(const float4*)&Qs[(ty * 4 + i) * AS + d0];
            #pragma unroll
            for (int j = 0; j < 4; j++) k[j] = *(const float4*)&Ks[(tx + 16 * j) * AS + d0];
            #pragma unroll
            for (int i = 0; i < 4; i++)
                #pragma unroll
                for (int j = 0; j < 4; j++)
                    s[i][j] += q[i].x * k[j].x + q[i].y * k[j].y
                             + q[i].z * k[j].z + q[i].w * k[j].w;
        }

        // ---- online softmax update ----
        #pragma unroll
        for (int i = 0; i < 4; i++) {
            float mx = -1e30f;
            #pragma unroll
            for (int j = 0; j < 4; j++) { s[i][j] *= 0.125f; mx = fmaxf(mx, s[i][j]); }
            #pragma unroll
            for (int o = 1; o < 16; o <<= 1)
                mx = fmaxf(mx, __shfl_xor_sync(0xffffffffu, mx, o));
            float mnew  = fmaxf(m[i], mx);
            float alpha = __expf(m[i] - mnew);
            float rs = 0.f;
            #pragma unroll
            for (int j = 0; j < 4; j++) { s[i][j] = __expf(s[i][j] - mnew); rs += s[i][j]; }
            #pragma unroll
            for (int o = 1; o < 16; o <<= 1)
                rs += __shfl_xor_sync(0xffffffffu, rs, o);
            l[i] = l[i] * alpha + rs;
            m[i] = mnew;
            #pragma unroll
            for (int j = 0; j < 4; j++) {
                O[i][j] *= alpha;
                Ps[(ty * 4 + i) * AS + tx + 16 * j] = s[i][j];
            }
        }
        __syncthreads();

        // ---- O += P @ V (O cols d_j = tx*4 + j) ----
        #pragma unroll
        for (int c0 = 0; c0 < 64; c0 += 4) {
            float4 p[4];
            #pragma unroll
            for (int i = 0; i < 4; i++) p[i] = *(const float4*)&Ps[(ty * 4 + i) * AS + c0];
            #pragma unroll
            for (int cc = 0; cc < 4; cc++) {
                float4 v = *(const float4*)&Vs[(c0 + cc) * AS + tx * 4];
                #pragma unroll
                for (int i = 0; i < 4; i++) {
                    float pv = (cc == 0) ? p[i].x : (cc == 1) ? p[i].y
                             : (cc == 2) ? p[i].z : p[i].w;
                    O[i][0] += pv * v.x; O[i][1] += pv * v.y;
                    O[i][2] += pv * v.z; O[i][3] += pv * v.w;
                }
            }
        }
    }

    // epilogue: out[b, q0+row, h*64 + tx*4 ..] = O / l
    #pragma unroll
    for (int i = 0; i < 4; i++) {
        float inv = 1.0f / l[i];
        int row = q0 + ty * 4 + i;
        float4 o;
        o.x = O[i][0] * inv; o.y = O[i][1] * inv;
        o.z = O[i][2] * inv; o.w = O[i][3] * inv;
        *(float4*)&out[((size_t)b * Nseq + row) * Emb + h * HDm + tx * 4] = o;
    }
}

#define ATTN_SMEM (4 * 64 * AS * 4)   // 69632 bytes

// ---------------- launch ----------------------------------------------------
extern "C" void kernel_launch(void* const* d_in, const int* in_sizes, int n_in,
                              void* d_out, int out_size)
{
    (void)in_sizes; (void)n_in; (void)out_size;
    const float* x        = (const float*)d_in[0];
    const float* qkv_w    = (const float*)d_in[1];
    const float* qkv_b    = (const float*)d_in[2];
    const float* fc1_w    = (const float*)d_in[3];
    const float* fc1_b    = (const float*)d_in[4];
    const float* fc2_w    = (const float*)d_in[5];
    const float* fc2_b    = (const float*)d_in[6];
    const float* ln_att_g = (const float*)d_in[7];
    const float* ln_att_b = (const float*)d_in[8];
    const float* ln_ffn_g = (const float*)d_in[9];
    const float* ln_ffn_b = (const float*)d_in[10];
    float* out = (float*)d_out;

    float *xn, *qkv, *x1, *xn2, *hid;
    cudaGetSymbolAddress((void**)&xn,  g_xn);
    cudaGetSymbolAddress((void**)&qkv, g_qkv);
    cudaGetSymbolAddress((void**)&x1,  g_x1);
    cudaGetSymbolAddress((void**)&xn2, g_xn2);
    cudaGetSymbolAddress((void**)&hid, g_hid);

    cudaFuncSetAttribute(attn_kernel,
                         cudaFuncAttributeMaxDynamicSharedMemorySize, ATTN_SMEM);

    // 1) LN1: xn = LN(x)
    ln_kernel<<<ROWS, 256>>>(x, nullptr, ln_att_g, ln_att_b, xn, nullptr);

    // 2) QKV GEMM: qkv = xn @ qkv_w + qkv_b        [8192,512]x[512,1536]
    gemm_kernel<0, false><<<dim3(1536 / 128, ROWS / 128), 256>>>(
        xn, qkv_w, qkv_b, nullptr, qkv, ROWS, Emb, 3 * Emb);

    // 3) attention: xn (reused) = softmax(qk^T/8) v  per (b,h)
    attn_kernel<<<dim3(Nseq / 64, Bsz * Hn), 256, ATTN_SMEM>>>(qkv, xn);

    // 4) residual + LN2: x1 = attn_out + x ; xn2 = LN(x1)
    ln_kernel<<<ROWS, 256>>>(xn, x, ln_ffn_g, ln_ffn_b, xn2, x1);

    // 5) FC1 + GELU: hid = gelu(xn2 @ fc1_w + fc1_b)   [8192,512]x[512,1536]
    gemm_kernel<1, false><<<dim3(HID / 128, ROWS / 128), 256>>>(
        xn2, fc1_w, fc1_b, nullptr, hid, ROWS, Emb, HID);

    // 6) FC2 + bias + residual: out = hid @ fc2_w + fc2_b + x1
    gemm_kernel<0, true><<<dim3(Emb / 128, ROWS / 128), 256>>>(
        hid, fc2_w, fc2_b, x1, out, ROWS, HID, Emb);
}

// round 2
// speedup vs baseline: 1.5459x; 1.5459x over previous
#include <cuda_runtime.h>
#include <math.h>

#define Bsz   4
#define Nseq  2048
#define Emb   512
#define Hn    8
#define HDm   64
#define HID   1536
#define ROWS  (Bsz * Nseq)   // 8192

// ---------------- scratch (device globals; no allocation allowed) ----------
__device__ float g_xn [ROWS * Emb];
__device__ float g_qkv[ROWS * 3 * Emb];
__device__ float g_x1 [ROWS * Emb];
__device__ float g_xn2[ROWS * Emb];
__device__ float g_hid[ROWS * HID];

// ---------------- LayerNorm (optionally fused residual add) ----------------
__global__ void __launch_bounds__(256) ln_kernel(
    const float* __restrict__ x, const float* __restrict__ resid,
    const float* __restrict__ g, const float* __restrict__ bb,
    float* __restrict__ out, float* __restrict__ xsum)
{
    int row = blockIdx.x;
    int tid = threadIdx.x;
    const float2* xr = (const float2*)(x + (size_t)row * Emb);
    float2 v = xr[tid];
    if (resid) {
        const float2* rr = (const float2*)(resid + (size_t)row * Emb);
        float2 r = rr[tid];
        v.x += r.x; v.y += r.y;
        ((float2*)(xsum + (size_t)row * Emb))[tid] = v;
    }
    float s  = v.x + v.y;
    float sq = v.x * v.x + v.y * v.y;
    #pragma unroll
    for (int o = 16; o > 0; o >>= 1) {
        s  += __shfl_xor_sync(0xffffffffu, s,  o);
        sq += __shfl_xor_sync(0xffffffffu, sq, o);
    }
    __shared__ float ss[8], sqs[8];
    int w = tid >> 5, lane = tid & 31;
    if (lane == 0) { ss[w] = s; sqs[w] = sq; }
    __syncthreads();
    float st = 0.f, sqt = 0.f;
    #pragma unroll
    for (int i = 0; i < 8; i++) { st += ss[i]; sqt += sqs[i]; }
    float mu   = st * (1.0f / Emb);
    float var  = sqt * (1.0f / Emb) - mu * mu;
    float rstd = rsqrtf(var + 1e-5f);
    float2 gg  = ((const float2*)g)[tid];
    float2 bv  = ((const float2*)bb)[tid];
    float2 o;
    o.x = (v.x - mu) * rstd * gg.x + bv.x;
    o.y = (v.y - mu) * rstd * gg.y + bv.y;
    ((float2*)(out + (size_t)row * Emb))[tid] = o;
}

// ---------------- GELU (exact, erf) ----------------------------------------
__device__ __forceinline__ float gelu_exact(float x) {
    return 0.5f * x * (1.0f + erff(x * 0.70710678118654752f));
}

// ---------------- TF32 helpers ----------------------------------------------
__device__ __forceinline__ float tf32r(float x) {
    unsigned u;
    asm("cvt.rna.tf32.f32 %0, %1;" : "=r"(u) : "f"(x));
    return __uint_as_float(u);
}
__device__ __forceinline__ float4 tf32r4(float4 v) {
    float4 r;
    r.x = tf32r(v.x); r.y = tf32r(v.y); r.z = tf32r(v.z); r.w = tf32r(v.w);
    return r;
}
__device__ __forceinline__ void mma_tf32(
    float* d, const unsigned* a, const unsigned* b)
{
    asm volatile(
        "mma.sync.aligned.m16n8k8.row.col.f32.tf32.tf32.f32 "
        "{%0,%1,%2,%3}, {%4,%5,%6,%7}, {%8,%9}, {%0,%1,%2,%3};"
        : "+f"(d[0]), "+f"(d[1]), "+f"(d[2]), "+f"(d[3])
        : "r"(a[0]), "r"(a[1]), "r"(a[2]), "r"(a[3]),
          "r"(b[0]), "r"(b[1]));
}

// ---------------- TF32 tensor-core GEMM -------------------------------------
// C[M,N] = A[M,K] @ W[K,N] + bias (+gelu)(+resid)
// CTA tile 128x128, BK=32, 256 threads = 8 warps, warp tile 32x64 (grid 4x2).
// SMEM strides padded so fragment LDS is bank-conflict-free:
//   As stride 36  (36%32=4 -> bank = 4*(lane/4)+lane%4 = lane)
//   Bs stride 136 (136%32=8 -> bank = 8*(lane%4)+lane/4, all distinct)
// Register-staged double buffering; tf32 rounding (rna) applied at STS.
#define AST 36
#define BST 136
#define GEMM_SMEM ((2 * 128 * AST + 2 * 32 * BST) * 4)   // 71680 B

template<int ACT, bool RES>
__global__ void __launch_bounds__(256) tf32_gemm_kernel(
    const float* __restrict__ A, const float* __restrict__ W,
    const float* __restrict__ bias, const float* __restrict__ R,
    float* __restrict__ C, int M, int K, int N)
{
    extern __shared__ float sm[];
    float* As = sm;                    // [2][128*AST]
    float* Bs = sm + 2 * 128 * AST;    // [2][32*BST]

    int tid  = threadIdx.x;
    int lane = tid & 31;
    int wid  = tid >> 5;
    int wm   = wid & 3;      // warp row  (0..3) -> rows wm*32
    int wn   = wid >> 2;     // warp col  (0..1) -> cols wn*64
    int bm   = blockIdx.y, bn = blockIdx.x;
    int g    = lane >> 2, q = lane & 3;

    // global load mapping
    int ar  = tid >> 3;            // A row within tile, +32*r
    int ac  = (tid & 7) * 4;       // A col (k) float4
    int br  = tid >> 5;            // B row (k) within tile, +8*r
    int bc  = (tid & 31) * 4;      // B col float4
    const float* Ag = A + ((size_t)(bm * 128 + ar)) * K + ac;
    const float* Wg = W + (size_t)br * N + (size_t)bn * 128 + bc;

    float4 pa[4], pb[4];
    #define LOAD_TILE(k0)                                                   \
        {                                                                   \
            _Pragma("unroll")                                               \
            for (int r = 0; r < 4; r++) {                                   \
                pa[r] = *(const float4*)(Ag + (size_t)(r * 32) * K + (k0)); \
                pb[r] = *(const float4*)(Wg + (size_t)((k0) + r * 8) * N);  \
            }                                                               \
        }
    #define STORE_TILE(buf)                                                 \
        {                                                                   \
            _Pragma("unroll")                                               \
            for (int r = 0; r < 4; r++) {                                   \
                *(float4*)&As[(buf) * 128 * AST + (ar + r * 32) * AST + ac] \
                    = tf32r4(pa[r]);                                        \
                *(float4*)&Bs[(buf) * 32 * BST + (br + r * 8) * BST + bc]   \
                    = tf32r4(pb[r]);                                        \
            }                                                               \
        }

    float acc[2][8][4] = {};

    LOAD_TILE(0);
    STORE_TILE(0);
    __syncthreads();

    int NT = K / 32;
    for (int it = 0; it < NT; it++) {
        int nxt = it + 1;
        if (nxt < NT) LOAD_TILE(nxt * 32);

        const unsigned* asu = (const unsigned*)(As + (it & 1) * 128 * AST)
                              + wm * 32 * AST;
        const unsigned* bsu = (const unsigned*)(Bs + (it & 1) * 32 * BST)
                              + wn * 64;
        #pragma unroll
        for (int k8 = 0; k8 < 4; k8++) {
            int kk = k8 * 8;
            unsigned a[2][4], b[8][2];
            #pragma unroll
            for (int mf = 0; mf < 2; mf++) {
                a[mf][0] = asu[(mf * 16 + g)     * AST + kk + q];
                a[mf][1] = asu[(mf * 16 + g + 8) * AST + kk + q];
                a[mf][2] = asu[(mf * 16 + g)     * AST + kk + q + 4];
                a[mf][3] = asu[(mf * 16 + g + 8) * AST + kk + q + 4];
            }
            #pragma unroll
            for (int nf = 0; nf < 8; nf++) {
                b[nf][0] = bsu[(kk + q)     * BST + nf * 8 + g];
                b[nf][1] = bsu[(kk + q + 4) * BST + nf * 8 + g];
            }
            #pragma unroll
            for (int mf = 0; mf < 2; mf++)
                #pragma unroll
                for (int nf = 0; nf < 8; nf++)
                    mma_tf32(acc[mf][nf], a[mf], b[nf]);
        }

        __syncthreads();
        if (nxt < NT) {
            STORE_TILE(nxt & 1);
            __syncthreads();
        }
    }

    // epilogue
    int row0 = bm * 128 + wm * 32 + g;
    int col0 = bn * 128 + wn * 64 + 2 * q;
    #pragma unroll
    for (int nf = 0; nf < 8; nf++) {
        int c = col0 + nf * 8;
        float bx = bias[c], by = bias[c + 1];
        #pragma unroll
        for (int mf = 0; mf < 2; mf++) {
            int r0 = row0 + mf * 16;
            float v0x = acc[mf][nf][0] + bx;
            float v0y = acc[mf][nf][1] + by;
            float v1x = acc[mf][nf][2] + bx;
            float v1y = acc[mf][nf][3] + by;
            if (ACT == 1) {
                v0x = gelu_exact(v0x); v0y = gelu_exact(v0y);
                v1x = gelu_exact(v1x); v1y = gelu_exact(v1y);
            }
            if (RES) {
                const float2 r0v = *(const float2*)&R[(size_t)r0 * N + c];
                const float2 r1v = *(const float2*)&R[(size_t)(r0 + 8) * N + c];
                v0x += r0v.x; v0y += r0v.y;
                v1x += r1v.x; v1y += r1v.y;
            }
            float2 o0 = {v0x, v0y}, o1 = {v1x, v1y};
            *(float2*)&C[(size_t)r0 * N + c]       = o0;
            *(float2*)&C[(size_t)(r0 + 8) * N + c] = o1;
        }
    }
    #undef LOAD_TILE
    #undef STORE_TILE
}

// ---------------- flash attention, fp32 (unchanged from R1) -----------------
#define AS 68

__global__ void __launch_bounds__(256) attn_kernel(
    const float* __restrict__ qkv, float* __restrict__ out)
{
    extern __shared__ float sm[];
    float* Qs = sm;
    float* Ks = Qs + 64 * AS;
    float* Vs = Ks + 64 * AS;
    float* Ps = Vs + 64 * AS;

    int tid = threadIdx.x;
    int bh = blockIdx.y;
    int b = bh >> 3, h = bh & 7;
    int q0 = blockIdx.x * 64;
    const float* base = qkv + (size_t)b * Nseq * (3 * Emb) + h * (3 * HDm);

    #pragma unroll
    for (int r = 0; r < 8; r++) {
        int fi  = tid + r * 256;
        int row = fi >> 5;
        int c2  = (fi & 31) * 2;
        float2 v = *(const float2*)(base + (size_t)(q0 + row) * (3 * Emb) + c2);
        *(float2*)&Qs[row * AS + c2] = v;
    }

    int ty = tid >> 4;
    int tx = tid & 15;
    float O[4][4] = {};
    float m[4], l[4];
    #pragma unroll
    for (int i = 0; i < 4; i++) { m[i] = -1e30f; l[i] = 0.f; }

    for (int kb = 0; kb < Nseq / 64; kb++) {
        __syncthreads();
        #pragma unroll
        for (int r = 0; r < 8; r++) {
            int fi  = tid + r * 256;
            int row = fi >> 5;
            int c2  = (fi & 31) * 2;
            const float* gp = base + (size_t)(kb * 64 + row) * (3 * Emb);
            *(float2*)&Ks[row * AS + c2] = *(const float2*)(gp + HDm + c2);
            *(float2*)&Vs[row * AS + c2] = *(const float2*)(gp + 2 * HDm + c2);
        }
        __syncthreads();

        float s[4][4] = {};
        #pragma unroll
        for (int d0 = 0; d0 < 64; d0 += 4) {
            float4 qv[4], kv[4];
            #pragma unroll
            for (int i = 0; i < 4; i++) qv[i] = *(const float4*)&Qs[(ty * 4 + i) * AS + d0];
            #pragma unroll
            for (int j = 0; j < 4; j++) kv[j] = *(const float4*)&Ks[(tx + 16 * j) * AS + d0];
            #pragma unroll
            for (int i = 0; i < 4; i++)
                #pragma unroll
                for (int j = 0; j < 4; j++)
                    s[i][j] += qv[i].x * kv[j].x + qv[i].y * kv[j].y
                             + qv[i].z * kv[j].z + qv[i].w * kv[j].w;
        }

        #pragma unroll
        for (int i = 0; i < 4; i++) {
            float mx = -1e30f;
            #pragma unroll
            for (int j = 0; j < 4; j++) { s[i][j] *= 0.125f; mx = fmaxf(mx, s[i][j]); }
            #pragma unroll
            for (int o = 1; o < 16; o <<= 1)
                mx = fmaxf(mx, __shfl_xor_sync(0xffffffffu, mx, o));
            float mnew  = fmaxf(m[i], mx);
            float alpha = __expf(m[i] - mnew);
            float rs = 0.f;
            #pragma unroll
            for (int j = 0; j < 4; j++) { s[i][j] = __expf(s[i][j] - mnew); rs += s[i][j]; }
            #pragma unroll
            for (int o = 1; o < 16; o <<= 1)
                rs += __shfl_xor_sync(0xffffffffu, rs, o);
            l[i] = l[i] * alpha + rs;
            m[i] = mnew;
            #pragma unroll
            for (int j = 0; j < 4; j++) {
                O[i][j] *= alpha;
                Ps[(ty * 4 + i) * AS + tx + 16 * j] = s[i][j];
            }
        }
        __syncthreads();

        #pragma unroll
        for (int c0 = 0; c0 < 64; c0 += 4) {
            float4 p[4];
            #pragma unroll
            for (int i = 0; i < 4; i++) p[i] = *(const float4*)&Ps[(ty * 4 + i) * AS + c0];
            #pragma unroll
            for (int cc = 0; cc < 4; cc++) {
                float4 v = *(const float4*)&Vs[(c0 + cc) * AS + tx * 4];
                #pragma unroll
                for (int i = 0; i < 4; i++) {
                    float pv = (cc == 0) ? p[i].x : (cc == 1) ? p[i].y
                             : (cc == 2) ? p[i].z : p[i].w;
                    O[i][0] += pv * v.x; O[i][1] += pv * v.y;
                    O[i][2] += pv * v.z; O[i][3] += pv * v.w;
                }
            }
        }
    }

    #pragma unroll
    for (int i = 0; i < 4; i++) {
        float inv = 1.0f / l[i];
        int row = q0 + ty * 4 + i;
        float4 o;
        o.x = O[i][0] * inv; o.y = O[i][1] * inv;
        o.z = O[i][2] * inv; o.w = O[i][3] * inv;
        *(float4*)&out[((size_t)b * Nseq + row) * Emb + h * HDm + tx * 4] = o;
    }
}

#define ATTN_SMEM (4 * 64 * AS * 4)

// ---------------- launch ----------------------------------------------------
extern "C" void kernel_launch(void* const* d_in, const int* in_sizes, int n_in,
                              void* d_out, int out_size)
{
    (void)in_sizes; (void)n_in; (void)out_size;
    const float* x        = (const float*)d_in[0];
    const float* qkv_w    = (const float*)d_in[1];
    const float* qkv_b    = (const float*)d_in[2];
    const float* fc1_w    = (const float*)d_in[3];
    const float* fc1_b    = (const float*)d_in[4];
    const float* fc2_w    = (const float*)d_in[5];
    const float* fc2_b    = (const float*)d_in[6];
    const float* ln_att_g = (const float*)d_in[7];
    const float* ln_att_b = (const float*)d_in[8];
    const float* ln_ffn_g = (const float*)d_in[9];
    const float* ln_ffn_b = (const float*)d_in[10];
    float* out = (float*)d_out;

    float *xn, *qkv, *x1, *xn2, *hid;
    cudaGetSymbolAddress((void**)&xn,  g_xn);
    cudaGetSymbolAddress((void**)&qkv, g_qkv);
    cudaGetSymbolAddress((void**)&x1,  g_x1);
    cudaGetSymbolAddress((void**)&xn2, g_xn2);
    cudaGetSymbolAddress((void**)&hid, g_hid);

    cudaFuncSetAttribute(attn_kernel,
                         cudaFuncAttributeMaxDynamicSharedMemorySize, ATTN_SMEM);
    cudaFuncSetAttribute(tf32_gemm_kernel<0, false>,
                         cudaFuncAttributeMaxDynamicSharedMemorySize, GEMM_SMEM);
    cudaFuncSetAttribute(tf32_gemm_kernel<1, false>,
                         cudaFuncAttributeMaxDynamicSharedMemorySize, GEMM_SMEM);
    cudaFuncSetAttribute(tf32_gemm_kernel<0, true>,
                         cudaFuncAttributeMaxDynamicSharedMemorySize, GEMM_SMEM);

    // 1) LN1
    ln_kernel<<<ROWS, 256>>>(x, nullptr, ln_att_g, ln_att_b, xn, nullptr);

    // 2) QKV GEMM (tf32 tensor cores)
    tf32_gemm_kernel<0, false><<<dim3(1536 / 128, ROWS / 128), 256, GEMM_SMEM>>>(
        xn, qkv_w, qkv_b, nullptr, qkv, ROWS, Emb, 3 * Emb);

    // 3) attention
    attn_kernel<<<dim3(Nseq / 64, Bsz * Hn), 256, ATTN_SMEM>>>(qkv, xn);

    // 4) residual + LN2
    ln_kernel<<<ROWS, 256>>>(xn, x, ln_ffn_g, ln_ffn_b, xn2, x1);

    // 5) FC1 + GELU (tf32)
    tf32_gemm_kernel<1, false><<<dim3(HID / 128, ROWS / 128), 256, GEMM_SMEM>>>(
        xn2, fc1_w, fc1_b, nullptr, hid, ROWS, Emb, HID);

    // 6) FC2 + bias + residual (tf32)
    tf32_gemm_kernel<0, true><<<dim3(Emb / 128, ROWS / 128), 256, GEMM_SMEM>>>(
        hid, fc2_w, fc2_b, x1, out, ROWS, HID, Emb);
}

// round 3
// speedup vs baseline: 2.9738x; 1.9237x over previous
#include <cuda_runtime.h>
#include <math.h>

#define Bsz   4
#define Nseq  2048
#define Emb   512
#define Hn    8
#define HDm   64
#define HID   1536
#define ROWS  (Bsz * Nseq)   // 8192

// ---------------- scratch (device globals; no allocation allowed) ----------
__device__ float g_xn [ROWS * Emb];
__device__ float g_qkv[ROWS * 3 * Emb];
__device__ float g_x1 [ROWS * Emb];
__device__ float g_xn2[ROWS * Emb];
__device__ float g_hid[ROWS * HID];

// ---------------- LayerNorm (optionally fused residual add) ----------------
__global__ void __launch_bounds__(256) ln_kernel(
    const float* __restrict__ x, const float* __restrict__ resid,
    const float* __restrict__ g, const float* __restrict__ bb,
    float* __restrict__ out, float* __restrict__ xsum)
{
    int row = blockIdx.x;
    int tid = threadIdx.x;
    const float2* xr = (const float2*)(x + (size_t)row * Emb);
    float2 v = xr[tid];
    if (resid) {
        const float2* rr = (const float2*)(resid + (size_t)row * Emb);
        float2 r = rr[tid];
        v.x += r.x; v.y += r.y;
        ((float2*)(xsum + (size_t)row * Emb))[tid] = v;
    }
    float s  = v.x + v.y;
    float sq = v.x * v.x + v.y * v.y;
    #pragma unroll
    for (int o = 16; o > 0; o >>= 1) {
        s  += __shfl_xor_sync(0xffffffffu, s,  o);
        sq += __shfl_xor_sync(0xffffffffu, sq, o);
    }
    __shared__ float ss[8], sqs[8];
    int w = tid >> 5, lane = tid & 31;
    if (lane == 0) { ss[w] = s; sqs[w] = sq; }
    __syncthreads();
    float st = 0.f, sqt = 0.f;
    #pragma unroll
    for (int i = 0; i < 8; i++) { st += ss[i]; sqt += sqs[i]; }
    float mu   = st * (1.0f / Emb);
    float var  = sqt * (1.0f / Emb) - mu * mu;
    float rstd = rsqrtf(var + 1e-5f);
    float2 gg  = ((const float2*)g)[tid];
    float2 bv  = ((const float2*)bb)[tid];
    float2 o;
    o.x = (v.x - mu) * rstd * gg.x + bv.x;
    o.y = (v.y - mu) * rstd * gg.y + bv.y;
    ((float2*)(out + (size_t)row * Emb))[tid] = o;
}

// ---------------- GELU (exact, erf) ----------------------------------------
__device__ __forceinline__ float gelu_exact(float x) {
    return 0.5f * x * (1.0f + erff(x * 0.70710678118654752f));
}

// ---------------- TF32 helpers ----------------------------------------------
__device__ __forceinline__ float tf32r(float x) {
    unsigned u;
    asm("cvt.rna.tf32.f32 %0, %1;" : "=r"(u) : "f"(x));
    return __uint_as_float(u);
}
__device__ __forceinline__ float4 tf32r4(float4 v) {
    float4 r;
    r.x = tf32r(v.x); r.y = tf32r(v.y); r.z = tf32r(v.z); r.w = tf32r(v.w);
    return r;
}
__device__ __forceinline__ void mma_tf32(
    float* d, const unsigned* a, const unsigned* b)
{
    asm volatile(
        "mma.sync.aligned.m16n8k8.row.col.f32.tf32.tf32.f32 "
        "{%0,%1,%2,%3}, {%4,%5,%6,%7}, {%8,%9}, {%0,%1,%2,%3};"
        : "+f"(d[0]), "+f"(d[1]), "+f"(d[2]), "+f"(d[3])
        : "r"(a[0]), "r"(a[1]), "r"(a[2]), "r"(a[3]),
          "r"(b[0]), "r"(b[1]));
}

// ---------------- TF32 tensor-core GEMM (verified in R2) --------------------
#define AST 36
#define BST 136
#define GEMM_SMEM ((2 * 128 * AST + 2 * 32 * BST) * 4)   // 71680 B

template<int ACT, bool RES>
__global__ void __launch_bounds__(256) tf32_gemm_kernel(
    const float* __restrict__ A, const float* __restrict__ W,
    const float* __restrict__ bias, const float* __restrict__ R,
    float* __restrict__ C, int M, int K, int N)
{
    extern __shared__ float sm[];
    float* As = sm;
    float* Bs = sm + 2 * 128 * AST;

    int tid  = threadIdx.x;
    int lane = tid & 31;
    int wid  = tid >> 5;
    int wm   = wid & 3;
    int wn   = wid >> 2;
    int bm   = blockIdx.y, bn = blockIdx.x;
    int g    = lane >> 2, q = lane & 3;

    int ar  = tid >> 3;
    int ac  = (tid & 7) * 4;
    int br  = tid >> 5;
    int bc  = (tid & 31) * 4;
    const float* Ag = A + ((size_t)(bm * 128 + ar)) * K + ac;
    const float* Wg = W + (size_t)br * N + (size_t)bn * 128 + bc;

    float4 pa[4], pb[4];
    #define LOAD_TILE(k0)                                                   \
        {                                                                   \
            _Pragma("unroll")                                               \
            for (int r = 0; r < 4; r++) {                                   \
                pa[r] = *(const float4*)(Ag + (size_t)(r * 32) * K + (k0)); \
                pb[r] = *(const float4*)(Wg + (size_t)((k0) + r * 8) * N);  \
            }                                                               \
        }
    #define STORE_TILE(buf)                                                 \
        {                                                                   \
            _Pragma("unroll")                                               \
            for (int r = 0; r < 4; r++) {                                   \
                *(float4*)&As[(buf) * 128 * AST + (ar + r * 32) * AST + ac] \
                    = tf32r4(pa[r]);                                        \
                *(float4*)&Bs[(buf) * 32 * BST + (br + r * 8) * BST + bc]   \
                    = tf32r4(pb[r]);                                        \
            }                                                               \
        }

    float acc[2][8][4] = {};

    LOAD_TILE(0);
    STORE_TILE(0);
    __syncthreads();

    int NT = K / 32;
    for (int it = 0; it < NT; it++) {
        int nxt = it + 1;
        if (nxt < NT) LOAD_TILE(nxt * 32);

        const unsigned* asu = (const unsigned*)(As + (it & 1) * 128 * AST)
                              + wm * 32 * AST;
        const unsigned* bsu = (const unsigned*)(Bs + (it & 1) * 32 * BST)
                              + wn * 64;
        #pragma unroll
        for (int k8 = 0; k8 < 4; k8++) {
            int kk = k8 * 8;
            unsigned a[2][4], b[8][2];
            #pragma unroll
            for (int mf = 0; mf < 2; mf++) {
                a[mf][0] = asu[(mf * 16 + g)     * AST + kk + q];
                a[mf][1] = asu[(mf * 16 + g + 8) * AST + kk + q];
                a[mf][2] = asu[(mf * 16 + g)     * AST + kk + q + 4];
                a[mf][3] = asu[(mf * 16 + g + 8) * AST + kk + q + 4];
            }
            #pragma unroll
            for (int nf = 0; nf < 8; nf++) {
                b[nf][0] = bsu[(kk + q)     * BST + nf * 8 + g];
                b[nf][1] = bsu[(kk + q + 4) * BST + nf * 8 + g];
            }
            #pragma unroll
            for (int mf = 0; mf < 2; mf++)
                #pragma unroll
                for (int nf = 0; nf < 8; nf++)
                    mma_tf32(acc[mf][nf], a[mf], b[nf]);
        }

        __syncthreads();
        if (nxt < NT) {
            STORE_TILE(nxt & 1);
            __syncthreads();
        }
    }

    int row0 = bm * 128 + wm * 32 + g;
    int col0 = bn * 128 + wn * 64 + 2 * q;
    #pragma unroll
    for (int nf = 0; nf < 8; nf++) {
        int c = col0 + nf * 8;
        float bx = bias[c], by = bias[c + 1];
        #pragma unroll
        for (int mf = 0; mf < 2; mf++) {
            int r0 = row0 + mf * 16;
            float v0x = acc[mf][nf][0] + bx;
            float v0y = acc[mf][nf][1] + by;
            float v1x = acc[mf][nf][2] + bx;
            float v1y = acc[mf][nf][3] + by;
            if (ACT == 1) {
                v0x = gelu_exact(v0x); v0y = gelu_exact(v0y);
                v1x = gelu_exact(v1x); v1y = gelu_exact(v1y);
            }
            if (RES) {
                const float2 r0v = *(const float2*)&R[(size_t)r0 * N + c];
                const float2 r1v = *(const float2*)&R[(size_t)(r0 + 8) * N + c];
                v0x += r0v.x; v0y += r0v.y;
                v1x += r1v.x; v1y += r1v.y;
            }
            float2 o0 = {v0x, v0y}, o1 = {v1x, v1y};
            *(float2*)&C[(size_t)r0 * N + c]       = o0;
            *(float2*)&C[(size_t)(r0 + 8) * N + c] = o1;
        }
    }
    #undef LOAD_TILE
    #undef STORE_TILE
}

// ---------------- flash attention, TF32 tensor cores -------------------------
// grid (Nseq/64, B*H), 128 threads = 4 warps; warp w owns Q rows w*16..w*16+15.
// SMEM strides: Qs/Ks/Ps 68 (=4 mod 32: frag loads 4g+q conflict-free),
//               Vs 72 (=8 mod 32: V B-frag loads 8q+g conflict-free).
#define QST 68
#define KST 68
#define VST 72
#define PST 68
#define ATTN_SMEM ((64 * QST + 64 * KST + 64 * VST + 64 * PST) * 4)  // 70656 B

__global__ void __launch_bounds__(128) attn_mma_kernel(
    const float* __restrict__ qkv, float* __restrict__ out)
{
    extern __shared__ float sm[];
    float* Qs = sm;
    float* Ks = Qs + 64 * QST;
    float* Vs = Ks + 64 * KST;
    float* Ps = Vs + 64 * VST;

    int tid  = threadIdx.x;
    int lane = tid & 31;
    int w    = tid >> 5;           // warp 0..3 -> q rows w*16..
    int g    = lane >> 2, q = lane & 3;

    int bh = blockIdx.y;
    int b  = bh >> 3, h = bh & 7;
    int q0 = blockIdx.x * 64;
    const float* base = qkv + (size_t)b * Nseq * (3 * Emb) + h * (3 * HDm);

    // ---- load Q tile (64x64), tf32-rounded ----
    #pragma unroll
    for (int i = 0; i < 8; i++) {
        int fi  = tid + i * 128;
        int row = fi >> 4;
        int c4  = (fi & 15) * 4;
        float4 v = *(const float4*)(base + (size_t)(q0 + row) * (3 * Emb) + c4);
        *(float4*)&Qs[row * QST + c4] = tf32r4(v);
    }

    float O[8][4] = {};
    float m0 = -1e30f, m1 = -1e30f, l0 = 0.f, l1 = 0.f;

    for (int kb = 0; kb < Nseq / 64; kb++) {
        __syncthreads();   // previous iter's Ks/Vs reads done
        #pragma unroll
        for (int i = 0; i < 8; i++) {
            int fi  = tid + i * 128;
            int row = fi >> 4;
            int c4  = (fi & 15) * 4;
            const float* gp = base + (size_t)(kb * 64 + row) * (3 * Emb);
            *(float4*)&Ks[row * KST + c4] = tf32r4(*(const float4*)(gp + HDm + c4));
            *(float4*)&Vs[row * VST + c4] = tf32r4(*(const float4*)(gp + 2 * HDm + c4));
        }
        __syncthreads();

        // ---- S = Q K^T : warp computes 16x64 ----
        const unsigned* qsu = (const unsigned*)Qs + (w * 16) * QST;
        unsigned af[8][4];
        #pragma unroll
        for (int k8 = 0; k8 < 8; k8++) {
            int kk = k8 * 8;
            af[k8][0] = qsu[(g)     * QST + kk + q];
            af[k8][1] = qsu[(g + 8) * QST + kk + q];
            af[k8][2] = qsu[(g)     * QST + kk + q + 4];
            af[k8][3] = qsu[(g + 8) * QST + kk + q + 4];
        }
        float sacc[8][4] = {};
        const unsigned* ksu = (const unsigned*)Ks;
        #pragma unroll
        for (int nf = 0; nf < 8; nf++) {
            #pragma unroll
            for (int k8 = 0; k8 < 8; k8++) {
                unsigned bfr[2];
                bfr[0] = ksu[(nf * 8 + g) * KST + k8 * 8 + q];
                bfr[1] = ksu[(nf * 8 + g) * KST + k8 * 8 + q + 4];
                mma_tf32(sacc[nf], af[k8], bfr);
            }
        }

        // ---- online softmax on C-fragments ----
        float mx0 = -1e30f, mx1 = -1e30f;
        #pragma unroll
        for (int nf = 0; nf < 8; nf++) {
            sacc[nf][0] *= 0.125f; sacc[nf][1] *= 0.125f;
            sacc[nf][2] *= 0.125f; sacc[nf][3] *= 0.125f;
            mx0 = fmaxf(mx0, fmaxf(sacc[nf][0], sacc[nf][1]));
            mx1 = fmaxf(mx1, fmaxf(sacc[nf][2], sacc[nf][3]));
        }
        mx0 = fmaxf(mx0, __shfl_xor_sync(0xffffffffu, mx0, 1));
        mx0 = fmaxf(mx0, __shfl_xor_sync(0xffffffffu, mx0, 2));
        mx1 = fmaxf(mx1, __shfl_xor_sync(0xffffffffu, mx1, 1));
        mx1 = fmaxf(mx1, __shfl_xor_sync(0xffffffffu, mx1, 2));

        float mn0 = fmaxf(m0, mx0), mn1 = fmaxf(m1, mx1);
        float al0 = __expf(m0 - mn0), al1 = __expf(m1 - mn1);
        m0 = mn0; m1 = mn1;

        float rs0 = 0.f, rs1 = 0.f;
        float* pw = Ps + (w * 16) * PST;
        #pragma unroll
        for (int nf = 0; nf < 8; nf++) {
            float p0 = __expf(sacc[nf][0] - mn0);
            float p1 = __expf(sacc[nf][1] - mn0);
            float p2 = __expf(sacc[nf][2] - mn1);
            float p3 = __expf(sacc[nf][3] - mn1);
            rs0 += p0 + p1; rs1 += p2 + p3;
            pw[(g)     * PST + nf * 8 + 2 * q]     = tf32r(p0);
            pw[(g)     * PST + nf * 8 + 2 * q + 1] = tf32r(p1);
            pw[(g + 8) * PST + nf * 8 + 2 * q]     = tf32r(p2);
            pw[(g + 8) * PST + nf * 8 + 2 * q + 1] = tf32r(p3);
        }
        rs0 += __shfl_xor_sync(0xffffffffu, rs0, 1);
        rs0 += __shfl_xor_sync(0xffffffffu, rs0, 2);
        rs1 += __shfl_xor_sync(0xffffffffu, rs1, 1);
        rs1 += __shfl_xor_sync(0xffffffffu, rs1, 2);
        l0 = l0 * al0 + rs0;
        l1 = l1 * al1 + rs1;

        #pragma unroll
        for (int df = 0; df < 8; df++) {
            O[df][0] *= al0; O[df][1] *= al0;
            O[df][2] *= al1; O[df][3] *= al1;
        }
        __syncwarp();   // Ps rows w*16.. written/read by this warp only

        // ---- O += P V : A-frags from Ps, B-frags from Vs ----
        const unsigned* psu = (const unsigned*)Ps + (w * 16) * PST;
        unsigned pf[8][4];
        #pragma unroll
        for (int k8 = 0; k8 < 8; k8++) {
            int kk = k8 * 8;
            pf[k8][0] = psu[(g)     * PST + kk + q];
            pf[k8][1] = psu[(g + 8) * PST + kk + q];
            pf[k8][2] = psu[(g)     * PST + kk + q + 4];
            pf[k8][3] = psu[(g + 8) * PST + kk + q + 4];
        }
        const unsigned* vsu = (const unsigned*)Vs;
        #pragma unroll
        for (int df = 0; df < 8; df++) {
            #pragma unroll
            for (int k8 = 0; k8 < 8; k8++) {
                unsigned bfr[2];
                bfr[0] = vsu[(k8 * 8 + q)     * VST + df * 8 + g];
                bfr[1] = vsu[(k8 * 8 + q + 4) * VST + df * 8 + g];
                mma_tf32(O[df], pf[k8], bfr);
            }
        }
    }

    // ---- epilogue: normalize and store ----
    float inv0 = 1.0f / l0, inv1 = 1.0f / l1;
    int r0 = q0 + w * 16 + g;
    int r1 = r0 + 8;
    #pragma unroll
    for (int df = 0; df < 8; df++) {
        int c = h * HDm + df * 8 + 2 * q;
        float2 o0 = {O[df][0] * inv0, O[df][1] * inv0};
        float2 o1 = {O[df][2] * inv1, O[df][3] * inv1};
        *(float2*)&out[((size_t)b * Nseq + r0) * Emb + c] = o0;
        *(float2*)&out[((size_t)b * Nseq + r1) * Emb + c] = o1;
    }
}

// ---------------- launch ----------------------------------------------------
extern "C" void kernel_launch(void* const* d_in, const int* in_sizes, int n_in,
                              void* d_out, int out_size)
{
    (void)in_sizes; (void)n_in; (void)out_size;
    const float* x        = (const float*)d_in[0];
    const float* qkv_w    = (const float*)d_in[1];
    const float* qkv_b    = (const float*)d_in[2];
    const float* fc1_w    = (const float*)d_in[3];
    const float* fc1_b    = (const float*)d_in[4];
    const float* fc2_w    = (const float*)d_in[5];
    const float* fc2_b    = (const float*)d_in[6];
    const float* ln_att_g = (const float*)d_in[7];
    const float* ln_att_b = (const float*)d_in[8];
    const float* ln_ffn_g = (const float*)d_in[9];
    const float* ln_ffn_b = (const float*)d_in[10];
    float* out = (float*)d_out;

    float *xn, *qkv, *x1, *xn2, *hid;
    cudaGetSymbolAddress((void**)&xn,  g_xn);
    cudaGetSymbolAddress((void**)&qkv, g_qkv);
    cudaGetSymbolAddress((void**)&x1,  g_x1);
    cudaGetSymbolAddress((void**)&xn2, g_xn2);
    cudaGetSymbolAddress((void**)&hid, g_hid);

    cudaFuncSetAttribute(attn_mma_kernel,
                         cudaFuncAttributeMaxDynamicSharedMemorySize, ATTN_SMEM);
    cudaFuncSetAttribute(tf32_gemm_kernel<0, false>,
                         cudaFuncAttributeMaxDynamicSharedMemorySize, GEMM_SMEM);
    cudaFuncSetAttribute(tf32_gemm_kernel<1, false>,
                         cudaFuncAttributeMaxDynamicSharedMemorySize, GEMM_SMEM);
    cudaFuncSetAttribute(tf32_gemm_kernel<0, true>,
                         cudaFuncAttributeMaxDynamicSharedMemorySize, GEMM_SMEM);

    // 1) LN1
    ln_kernel<<<ROWS, 256>>>(x, nullptr, ln_att_g, ln_att_b, xn, nullptr);

    // 2) QKV GEMM (tf32)
    tf32_gemm_kernel<0, false><<<dim3(1536 / 128, ROWS / 128), 256, GEMM_SMEM>>>(
        xn, qkv_w, qkv_b, nullptr, qkv, ROWS, Emb, 3 * Emb);

    // 3) attention (tf32 mma flash)
    attn_mma_kernel<<<dim3(Nseq / 64, Bsz * Hn), 128, ATTN_SMEM>>>(qkv, xn);

    // 4) residual + LN2
    ln_kernel<<<ROWS, 256>>>(xn, x, ln_ffn_g, ln_ffn_b, xn2, x1);

    // 5) FC1 + GELU (tf32)
    tf32_gemm_kernel<1, false><<<dim3(HID / 128, ROWS / 128), 256, GEMM_SMEM>>>(
        xn2, fc1_w, fc1_b, nullptr, hid, ROWS, Emb, HID);

    // 6) FC2 + bias + residual (tf32)
    tf32_gemm_kernel<0, true><<<dim3(Emb / 128, ROWS / 128), 256, GEMM_SMEM>>>(
        hid, fc2_w, fc2_b, x1, out, ROWS, HID, Emb);
}